// round 7
// baseline (speedup 1.0000x reference)
#include <cuda_runtime.h>
#include <math.h>

// AnomalyAttention: B=2, L=2048, H=8, E=64, band |i-j| <= 63.
// out = concat( V [B,L,H,E] f32 , series [B,H,L,L] f32 ).
// RT=32-row tiles, 256 threads (8 warps x 4 rows), 2 CTAs/SM.
// Series row = [0,wbase) zeros | 160-col window from smem | zeros, via cp.async.bulk.
// Swin aliases Ks (Ks dead after GEMM1; __syncthreads separates).

#define BN 2
#define HN 8
#define LN 2048
#define EN 64
#define RT 32          // rows per block
#define WWIN 160       // window width (RT + 128)
#define KSTR 68        // Q/K smem row stride (68%32=4 -> LDS.128 conflict-free)
#define VTSTR 164      // VT row stride (164%32=4 -> conflict-free; 160 data + 4 zero pad)
#define SWSTR 164      // Swin row stride
#define ZMAX 1888      // max zero-segment floats (LN - WWIN)
#define SCALE_L2E 0.18033688011112042f   // 0.125 * log2(e)

typedef unsigned long long u64;

__device__ __forceinline__ u64 fma2(u64 a, u64 b, u64 c) {
    u64 d;
    asm("fma.rn.f32x2 %0, %1, %2, %3;" : "=l"(d) : "l"(a), "l"(b), "l"(c));
    return d;
}
__device__ __forceinline__ float2 unpack2(u64 v) {
    float2 r;
    asm("mov.b64 {%0, %1}, %2;" : "=f"(r.x), "=f"(r.y) : "l"(v));
    return r;
}
__device__ __forceinline__ float ex2f(float x) {
    float y;
    asm("ex2.approx.ftz.f32 %0, %1;" : "=f"(y) : "f"(x));
    return y;
}
__device__ __forceinline__ unsigned smem_u32(const void* p) {
    return (unsigned)__cvta_generic_to_shared(p);
}
__device__ __forceinline__ void bulk_store(void* dst, unsigned src_smem, unsigned bytes) {
    asm volatile("cp.async.bulk.global.shared::cta.bulk_group [%0], [%1], %2;"
                 :: "l"(dst), "r"(src_smem), "r"(bytes) : "memory");
}

__global__ __launch_bounds__(256, 2)
void anomaly_attn_kernel(const float* __restrict__ Q,
                         const float* __restrict__ K,
                         const float* __restrict__ V,
                         float* __restrict__ out)
{
    extern __shared__ float sm[];
    float* Qs   = sm;                        // RT   * KSTR   (pre-scaled by 0.125*log2e)
    float* Ks   = Qs + RT * KSTR;            // WWIN * KSTR
    float* VT   = Ks + WWIN * KSTR;          // EN   * VTSTR  (VT[e][ww], pad cols zeroed)
    float* Zb   = VT + EN * VTSTR;           // ZMAX zeros
    float* Swin = Ks;                        // RT * SWSTR, ALIASES Ks (dead after GEMM1)

    const int bid = blockIdx.x;
    const int t   = bid & 63;
    const int h   = (bid >> 6) & 7;
    const int b   = bid >> 9;
    const int i0  = t * RT;
    const int wbase = min(max(i0 - 64, 0), LN - WWIN);

    const int tid  = threadIdx.x;
    const int lane = tid & 31;
    const int w    = tid >> 5;               // 8 warps x 4 rows
    const int ga   = 4 * w;
    const int gia  = i0 + ga;

    float* series = out + (size_t)BN * LN * HN * EN;
    const size_t growbase = (size_t)((b * HN + h) * LN);

    // ---- cooperative fills ----
    {
        const int e4 = (tid & 15) * 4;
        const int r0 = tid >> 4;             // 0..15
#pragma unroll
        for (int r = r0; r < RT; r += 16) {
            float4 q = *(const float4*)&Q[(((size_t)b * LN + (i0 + r)) * HN + h) * EN + e4];
            q.x *= SCALE_L2E; q.y *= SCALE_L2E; q.z *= SCALE_L2E; q.w *= SCALE_L2E;
            *(float4*)(Qs + r * KSTR + e4) = q;
        }
#pragma unroll
        for (int r = r0; r < WWIN; r += 16)
            *(float4*)(Ks + r * KSTR + e4) =
                *(const float4*)&K[(((size_t)b * LN + (wbase + r)) * HN + h) * EN + e4];

        // VT[e][j]: coalesced LDG.32 gather, conflict-free STS.128
        const int e  = tid & 63;
        const int jg = (tid >> 6) * 4;       // 0,4,8,12
#pragma unroll
        for (int j4 = jg; j4 < WWIN; j4 += 16) {
            const float* vp = &V[(((size_t)b * LN + (wbase + j4)) * HN + h) * EN + e];
            float4 v;
            v.x = vp[0];
            v.y = vp[HN * EN];
            v.z = vp[2 * HN * EN];
            v.w = vp[3 * HN * EN];
            *(float4*)(VT + e * VTSTR + j4) = v;
        }
        if (tid < EN)   // zero VT pad cols 160..163 (GEMM2 tail reads them)
            *(float4*)(VT + tid * VTSTR + WWIN) = make_float4(0.f, 0.f, 0.f, 0.f);
#pragma unroll
        for (int idx = tid; idx < ZMAX / 4; idx += 256)
            *(float4*)(Zb + idx * 4) = make_float4(0.f, 0.f, 0.f, 0.f);
    }
    __syncthreads();

    // ---- issue zero-segment bulk stores (overlap with all compute) ----
    if (lane == 0) {
        asm volatile("fence.proxy.async.shared::cta;" ::: "memory");
        const unsigned zb_addr = smem_u32(Zb);
        const unsigned lbytes = (unsigned)wbase * 4u;
        const unsigned rbytes = (unsigned)(LN - WWIN - wbase) * 4u;
#pragma unroll
        for (int r = 0; r < 4; r++) {
            float* rowp = series + (growbase + (gia + r)) * (size_t)LN;
            if (lbytes) bulk_store(rowp, zb_addr, lbytes);
            if (rbytes) bulk_store(rowp + wbase + WWIN, zb_addr, rbytes);
        }
    }

    // ---- per-warp geometry (window coords) ----
    const int jbase = max(0, gia - 63);
    const int g_hi  = min(LN - 1, gia + 66);
    const int spanw = g_hi - jbase;                 // <= 129
    const int off   = jbase - wbase;                // window col of jj=0

    // ---- GEMM1: scores[4][5] via LDS.128 + f32x2 FMA ----
    u64 acc[4][5];
#pragma unroll
    for (int r = 0; r < 4; r++)
#pragma unroll
        for (int s = 0; s < 5; s++) acc[r][s] = 0ull;

    const ulonglong2* kp[5];
#pragma unroll
    for (int s = 0; s < 5; s++) {
        const int row = min(off + lane + 32 * s, WWIN - 1);   // clamped lanes masked later
        kp[s] = (const ulonglong2*)(Ks + row * KSTR);
    }
    const ulonglong2* qp0 = (const ulonglong2*)(Qs + (ga + 0) * KSTR);
    const ulonglong2* qp1 = (const ulonglong2*)(Qs + (ga + 1) * KSTR);
    const ulonglong2* qp2 = (const ulonglong2*)(Qs + (ga + 2) * KSTR);
    const ulonglong2* qp3 = (const ulonglong2*)(Qs + (ga + 3) * KSTR);

#pragma unroll 4
    for (int e4 = 0; e4 < EN / 4; e4++) {
        const ulonglong2 q0 = qp0[e4], q1 = qp1[e4], q2 = qp2[e4], q3 = qp3[e4];
#pragma unroll
        for (int s = 0; s < 5; s++) {
            const ulonglong2 kk = kp[s][e4];
            acc[0][s] = fma2(q0.x, kk.x, acc[0][s]);
            acc[0][s] = fma2(q0.y, kk.y, acc[0][s]);
            acc[1][s] = fma2(q1.x, kk.x, acc[1][s]);
            acc[1][s] = fma2(q1.y, kk.y, acc[1][s]);
            acc[2][s] = fma2(q2.x, kk.x, acc[2][s]);
            acc[2][s] = fma2(q2.y, kk.y, acc[2][s]);
            acc[3][s] = fma2(q3.x, kk.x, acc[3][s]);
            acc[3][s] = fma2(q3.y, kk.y, acc[3][s]);
        }
    }

    // ---- pass 1: p = 2^(score), row sums (p kept in regs) ----
    float ps[4][5];
    float sum[4] = { 0.f, 0.f, 0.f, 0.f };
#pragma unroll
    for (int s = 0; s < 5; s++) {
        const int jj = lane + 32 * s;
        const int j  = jbase + jj;
#pragma unroll
        for (int r = 0; r < 4; r++) {
            const int gi = gia + r;
            const bool c = (jj <= spanw) && ((unsigned)(j - gi + 63) <= 126u);
            float p = 0.0f;
            if (c) {
                const float2 a = unpack2(acc[r][s]);
                p = ex2f(a.x + a.y);     // scale*log2e folded into Q
                sum[r] += p;
            }
            ps[r][s] = p;
        }
    }
#pragma unroll
    for (int o = 16; o > 0; o >>= 1)
#pragma unroll
        for (int r = 0; r < 4; r++)
            sum[r] += __shfl_xor_sync(0xffffffffu, sum[r], o);

    float rinv[4];
#pragma unroll
    for (int r = 0; r < 4; r++) rinv[r] = 1.0f / sum[r];

    // ---- all warps done reading Ks -> safe to reuse as Swin ----
    __syncthreads();

    // ---- zero this warp's Swin rows (4*SWSTR = 656 floats = 164 float4) ----
    {
        float4* z = (float4*)(Swin + ga * SWSTR);
        const float4 z4 = make_float4(0.f, 0.f, 0.f, 0.f);
#pragma unroll
        for (int k = 0; k < 6; k++) {
            const int idx = lane + 32 * k;
            if (idx < 164) z[idx] = z4;
        }
    }
    __syncwarp();

    // ---- pass 2: normalized p -> Swin (in-band only) ----
#pragma unroll
    for (int s = 0; s < 5; s++) {
        const int jj = lane + 32 * s;
        const int j  = jbase + jj;
#pragma unroll
        for (int r = 0; r < 4; r++) {
            const int gi = gia + r;
            const bool c = (jj <= spanw) && ((unsigned)(j - gi + 63) <= 126u);
            if (c) Swin[(ga + r) * SWSTR + off + jj] = ps[r][s] * rinv[r];
        }
    }
    __syncwarp();

    // ---- issue band-window bulk stores ----
    if (lane == 0) {
        asm volatile("fence.proxy.async.shared::cta;" ::: "memory");
#pragma unroll
        for (int r = 0; r < 4; r++) {
            float* rowp = series + (growbase + (gia + r)) * (size_t)LN + wbase;
            bulk_store(rowp, smem_u32(Swin + (ga + r) * SWSTR), WWIN * 4u);
        }
        asm volatile("cp.async.bulk.commit_group;" ::: "memory");
    }

    // ---- GEMM2: V_out[4][64] over window cols, LDS.128 everywhere ----
    u64 a0[4], a1[4];
#pragma unroll
    for (int r = 0; r < 4; r++) { a0[r] = 0ull; a1[r] = 0ull; }

    const int woff0 = off & ~3;
    const int niter = ((off + spanw - woff0) >> 2) + 1;     // <= 34
    const float* vt0 = VT + lane * VTSTR;
    const float* vt1 = VT + (lane + 32) * VTSTR;
#pragma unroll 2
    for (int it = 0; it < niter; it++) {
        const int ww = woff0 + 4 * it;
        const ulonglong2 v0 = *(const ulonglong2*)(vt0 + ww);
        const ulonglong2 v1 = *(const ulonglong2*)(vt1 + ww);
#pragma unroll
        for (int r = 0; r < 4; r++) {
            const ulonglong2 pr = *(const ulonglong2*)(Swin + (ga + r) * SWSTR + ww);
            a0[r] = fma2(pr.x, v0.x, a0[r]);
            a0[r] = fma2(pr.y, v0.y, a0[r]);
            a1[r] = fma2(pr.x, v1.x, a1[r]);
            a1[r] = fma2(pr.y, v1.y, a1[r]);
        }
    }
#pragma unroll
    for (int r = 0; r < 4; r++) {
        const int gi = gia + r;
        const size_t o = (((size_t)b * LN + gi) * HN + h) * EN;
        const float2 x0 = unpack2(a0[r]);
        const float2 x1 = unpack2(a1[r]);
        out[o + lane]      = x0.x + x0.y;     // p already normalized
        out[o + 32 + lane] = x1.x + x1.y;
    }

    // ---- drain async stores ----
    if (lane == 0)
        asm volatile("cp.async.bulk.wait_group 0;" ::: "memory");
}

extern "C" void kernel_launch(void* const* d_in, const int* in_sizes, int n_in,
                              void* d_out, int out_size) {
    const float* Q = (const float*)d_in[0];
    const float* K = (const float*)d_in[1];
    const float* V = (const float*)d_in[2];
    float* out = (float*)d_out;

    const int smem_bytes =
        (RT * KSTR + WWIN * KSTR + EN * VTSTR + ZMAX) * (int)sizeof(float);
    cudaFuncSetAttribute(anomaly_attn_kernel,
                         cudaFuncAttributeMaxDynamicSharedMemorySize, smem_bytes);

    dim3 grid(BN * HN * (LN / RT));   // 1024 blocks
    dim3 block(256);
    anomaly_attn_kernel<<<grid, block, smem_bytes>>>(Q, K, V, out);
}

// round 8
// speedup vs baseline: 1.2261x; 1.2261x over previous
#include <cuda_runtime.h>
#include <math.h>

// AnomalyAttention: B=2, L=2048, H=8, E=64, band |i-j| <= 63.
// out = concat( V [B,L,H,E] f32 , series [B,H,L,L] f32 ).
// Persistent kernel: 128 CTAs x 4 tiles, cross-tile pipelined:
//   - Q/K of tile n+1 prefetched via cp.async while softmax/GEMM2 of tile n runs
//   - series written via cp.async.bulk; window stores of tile n drain under tile n+1 GEMM1

#define BN 2
#define HN 8
#define LN 2048
#define EN 64
#define RT 64          // rows per tile
#define WWIN 192       // window width
#define KSTR 68        // Q/K smem row stride (68%32=4 -> LDS.128 conflict-free)
#define VTSTR 196      // VT row stride (192 data + 4 pad)
#define SWSTR 196      // Swin row stride
#define ZMAX 1856      // max zero-segment floats
#define GRID 128
#define TILES 512
#define SCALE_L2E 0.18033688011112042f   // 0.125 * log2(e)

typedef unsigned long long u64;

__device__ __forceinline__ u64 fma2(u64 a, u64 b, u64 c) {
    u64 d;
    asm("fma.rn.f32x2 %0, %1, %2, %3;" : "=l"(d) : "l"(a), "l"(b), "l"(c));
    return d;
}
__device__ __forceinline__ float2 unpack2(u64 v) {
    float2 r;
    asm("mov.b64 {%0, %1}, %2;" : "=f"(r.x), "=f"(r.y) : "l"(v));
    return r;
}
__device__ __forceinline__ float ex2f(float x) {
    float y;
    asm("ex2.approx.ftz.f32 %0, %1;" : "=f"(y) : "f"(x));
    return y;
}
__device__ __forceinline__ unsigned smem_u32(const void* p) {
    return (unsigned)__cvta_generic_to_shared(p);
}
__device__ __forceinline__ void bulk_store(void* dst, unsigned src_smem, unsigned bytes) {
    asm volatile("cp.async.bulk.global.shared::cta.bulk_group [%0], [%1], %2;"
                 :: "l"(dst), "r"(src_smem), "r"(bytes) : "memory");
}
__device__ __forceinline__ void cp16(float* dst_smem, const float* src) {
    asm volatile("cp.async.cg.shared.global [%0], [%1], 16;"
                 :: "r"(smem_u32(dst_smem)), "l"(src) : "memory");
}

__device__ __forceinline__ void issue_qk(const float* __restrict__ Q,
                                         const float* __restrict__ K,
                                         float* Qs, float* Ks,
                                         int b, int h, int i0, int wbase, int tid)
{
    const int e4 = (tid & 15) * 4;
    const int r0 = tid >> 4;             // 0..31
#pragma unroll
    for (int r = r0; r < RT; r += 32)
        cp16(Qs + r * KSTR + e4, &Q[(((size_t)b * LN + (i0 + r)) * HN + h) * EN + e4]);
#pragma unroll
    for (int r = r0; r < WWIN; r += 32)
        cp16(Ks + r * KSTR + e4, &K[(((size_t)b * LN + (wbase + r)) * HN + h) * EN + e4]);
    asm volatile("cp.async.commit_group;" ::: "memory");
}

__global__ __launch_bounds__(512, 1)
void anomaly_attn_kernel(const float* __restrict__ Q,
                         const float* __restrict__ K,
                         const float* __restrict__ V,
                         float* __restrict__ out)
{
    extern __shared__ float sm[];
    float* Qs   = sm;                        // RT   * KSTR
    float* Ks   = Qs + RT * KSTR;            // WWIN * KSTR
    float* VT   = Ks + WWIN * KSTR;          // EN   * VTSTR
    float* Swin = VT + EN * VTSTR;           // RT   * SWSTR
    float* Zb   = Swin + RT * SWSTR;         // ZMAX

    const int tid  = threadIdx.x;
    const int lane = tid & 31;
    const int w    = tid >> 5;               // 16 warps x 4 rows
    const int ga   = 4 * w;

    float* series = out + (size_t)BN * LN * HN * EN;

    // ---- one-time: zero buffer + VT pad cols ----
    for (int idx = tid; idx < ZMAX / 4; idx += 512)
        *(float4*)(Zb + idx * 4) = make_float4(0.f, 0.f, 0.f, 0.f);
    if (tid < EN)
        *(float4*)(VT + tid * VTSTR + WWIN) = make_float4(0.f, 0.f, 0.f, 0.f);

    // ---- first tile Q/K prefetch ----
    {
        const int T0 = blockIdx.x;
        const int t0 = T0 & 31, h0 = (T0 >> 5) & 7, b0 = T0 >> 8;
        const int i00 = t0 * RT;
        const int wb0 = min(max(i00 - 64, 0), LN - WWIN);
        issue_qk(Q, K, Qs, Ks, b0, h0, i00, wb0, tid);
    }
    __syncthreads();   // Zb visible to all (lane0 fences per tile before bulk)

    for (int T = blockIdx.x; T < TILES; T += GRID) {
        const int t  = T & 31;
        const int h  = (T >> 5) & 7;
        const int b  = T >> 8;
        const int i0 = t * RT;
        const int wbase = min(max(i0 - 64, 0), LN - WWIN);
        const int gia   = i0 + ga;
        const size_t growbase = (size_t)((b * HN + h) * LN);

        // ---- issue zero-segment bulk stores (Zb immutable -> never waited) ----
        if (lane == 0) {
            asm volatile("fence.proxy.async.shared::cta;" ::: "memory");
            const unsigned zb_addr = smem_u32(Zb);
            const unsigned lbytes = (unsigned)wbase * 4u;
            const unsigned rbytes = (unsigned)(LN - WWIN - wbase) * 4u;
#pragma unroll
            for (int r = 0; r < 4; r++) {
                float* rowp = series + (growbase + (gia + r)) * (size_t)LN;
                if (lbytes) bulk_store(rowp, zb_addr, lbytes);
                if (rbytes) bulk_store(rowp + wbase + WWIN, zb_addr, rbytes);
            }
            asm volatile("cp.async.bulk.commit_group;" ::: "memory");
        }

        // ---- Q/K (this tile) ready; also separates prev GEMM2 from VT refill ----
        asm volatile("cp.async.wait_group 0;" ::: "memory");
        __syncthreads();

        // ---- VT fill: VT[e][j] gather (coalesced LDG.32, STS.128) ----
        {
            const int e  = tid & 63;
            const int jg = (tid >> 6) * 4;   // 0..28
#pragma unroll
            for (int j4 = jg; j4 < WWIN; j4 += 32) {
                const float* vp = &V[(((size_t)b * LN + (wbase + j4)) * HN + h) * EN + e];
                float4 v;
                v.x = vp[0];
                v.y = vp[HN * EN];
                v.z = vp[2 * HN * EN];
                v.w = vp[3 * HN * EN];
                *(float4*)(VT + e * VTSTR + j4) = v;
            }
        }

        // ---- per-warp geometry ----
        const int jbase = max(0, gia - 63);
        const int g_hi  = min(LN - 1, gia + 66);
        const int spanw = g_hi - jbase;              // <= 129
        const int off   = jbase - wbase;

        // ---- GEMM1: scores[4][5], LDS.128 + f32x2 ----
        u64 acc[4][5];
#pragma unroll
        for (int r = 0; r < 4; r++)
#pragma unroll
            for (int s = 0; s < 5; s++) acc[r][s] = 0ull;

        const ulonglong2* kp[5];
#pragma unroll
        for (int s = 0; s < 5; s++) {
            const int row = min(off + lane + 32 * s, WWIN - 1);
            kp[s] = (const ulonglong2*)(Ks + row * KSTR);
        }
        const ulonglong2* qp0 = (const ulonglong2*)(Qs + (ga + 0) * KSTR);
        const ulonglong2* qp1 = (const ulonglong2*)(Qs + (ga + 1) * KSTR);
        const ulonglong2* qp2 = (const ulonglong2*)(Qs + (ga + 2) * KSTR);
        const ulonglong2* qp3 = (const ulonglong2*)(Qs + (ga + 3) * KSTR);

#pragma unroll 4
        for (int e4 = 0; e4 < EN / 4; e4++) {
            const ulonglong2 q0 = qp0[e4], q1 = qp1[e4], q2 = qp2[e4], q3 = qp3[e4];
#pragma unroll
            for (int s = 0; s < 5; s++) {
                const ulonglong2 kk = kp[s][e4];
                acc[0][s] = fma2(q0.x, kk.x, acc[0][s]);
                acc[0][s] = fma2(q0.y, kk.y, acc[0][s]);
                acc[1][s] = fma2(q1.x, kk.x, acc[1][s]);
                acc[1][s] = fma2(q1.y, kk.y, acc[1][s]);
                acc[2][s] = fma2(q2.x, kk.x, acc[2][s]);
                acc[2][s] = fma2(q2.y, kk.y, acc[2][s]);
                acc[3][s] = fma2(q3.x, kk.x, acc[3][s]);
                acc[3][s] = fma2(q3.y, kk.y, acc[3][s]);
            }
        }

        // ---- Ks dead + VT visible ----
        __syncthreads();

        // ---- prefetch next tile's Q/K (lands during softmax/GEMM2) ----
        {
            const int Tn = T + GRID;
            if (Tn < TILES) {
                const int tn = Tn & 31, hn = (Tn >> 5) & 7, bn = Tn >> 8;
                const int i0n = tn * RT;
                const int wbn = min(max(i0n - 64, 0), LN - WWIN);
                issue_qk(Q, K, Qs, Ks, bn, hn, i0n, wbn, tid);
            }
        }

        // ---- pass 1: p = 2^(scale*score), row sums ----
        float ps[4][5];
        float sum[4] = { 0.f, 0.f, 0.f, 0.f };
#pragma unroll
        for (int s = 0; s < 5; s++) {
            const int jj = lane + 32 * s;
            const int j  = jbase + jj;
#pragma unroll
            for (int r = 0; r < 4; r++) {
                const int gi = gia + r;
                const bool c = (jj <= spanw) && ((unsigned)(j - gi + 63) <= 126u);
                float p = 0.0f;
                if (c) {
                    const float2 a = unpack2(acc[r][s]);
                    p = ex2f((a.x + a.y) * SCALE_L2E);
                    sum[r] += p;
                }
                ps[r][s] = p;
            }
        }
#pragma unroll
        for (int o = 16; o > 0; o >>= 1)
#pragma unroll
            for (int r = 0; r < 4; r++)
                sum[r] += __shfl_xor_sync(0xffffffffu, sum[r], o);

        float rinv[4];
#pragma unroll
        for (int r = 0; r < 4; r++) rinv[r] = 1.0f / sum[r];

        // ---- ensure previous tile's window stores drained before rewriting Swin ----
        if (lane == 0)
            asm volatile("cp.async.bulk.wait_group 1;" ::: "memory");
        __syncwarp();

        // ---- zero this warp's Swin rows (196 float4) ----
        {
            float4* z = (float4*)(Swin + ga * SWSTR);
            const float4 z4 = make_float4(0.f, 0.f, 0.f, 0.f);
#pragma unroll
            for (int k = 0; k < 7; k++) {
                const int idx = lane + 32 * k;
                if (idx < 196) z[idx] = z4;
            }
        }
        __syncwarp();

        // ---- pass 2: normalized p -> Swin ----
#pragma unroll
        for (int s = 0; s < 5; s++) {
            const int jj = lane + 32 * s;
            const int j  = jbase + jj;
#pragma unroll
            for (int r = 0; r < 4; r++) {
                const int gi = gia + r;
                const bool c = (jj <= spanw) && ((unsigned)(j - gi + 63) <= 126u);
                if (c) Swin[(ga + r) * SWSTR + off + jj] = ps[r][s] * rinv[r];
            }
        }
        __syncwarp();

        // ---- window bulk stores ----
        if (lane == 0) {
            asm volatile("fence.proxy.async.shared::cta;" ::: "memory");
#pragma unroll
            for (int r = 0; r < 4; r++) {
                float* rowp = series + (growbase + (gia + r)) * (size_t)LN + wbase;
                bulk_store(rowp, smem_u32(Swin + (ga + r) * SWSTR), WWIN * 4u);
            }
            asm volatile("cp.async.bulk.commit_group;" ::: "memory");
        }

        // ---- GEMM2: V_out[4][64], LDS.128 ----
        u64 a0[4], a1[4];
#pragma unroll
        for (int r = 0; r < 4; r++) { a0[r] = 0ull; a1[r] = 0ull; }

        const int woff0 = off & ~3;
        const int niter = ((off + spanw - woff0) >> 2) + 1;
        const float* vt0 = VT + lane * VTSTR;
        const float* vt1 = VT + (lane + 32) * VTSTR;
#pragma unroll 2
        for (int it = 0; it < niter; it++) {
            const int ww = woff0 + 4 * it;
            const ulonglong2 v0 = *(const ulonglong2*)(vt0 + ww);
            const ulonglong2 v1 = *(const ulonglong2*)(vt1 + ww);
#pragma unroll
            for (int r = 0; r < 4; r++) {
                const ulonglong2 pr = *(const ulonglong2*)(Swin + (ga + r) * SWSTR + ww);
                a0[r] = fma2(pr.x, v0.x, a0[r]);
                a0[r] = fma2(pr.y, v0.y, a0[r]);
                a1[r] = fma2(pr.x, v1.x, a1[r]);
                a1[r] = fma2(pr.y, v1.y, a1[r]);
            }
        }
#pragma unroll
        for (int r = 0; r < 4; r++) {
            const int gi = gia + r;
            const size_t o = (((size_t)b * LN + gi) * HN + h) * EN;
            const float2 x0 = unpack2(a0[r]);
            const float2 x1 = unpack2(a1[r]);
            out[o + lane]      = x0.x + x0.y;
            out[o + 32 + lane] = x1.x + x1.y;
        }
    }

    // ---- drain all bulk stores before exit ----
    if (lane == 0)
        asm volatile("cp.async.bulk.wait_group 0;" ::: "memory");
}

extern "C" void kernel_launch(void* const* d_in, const int* in_sizes, int n_in,
                              void* d_out, int out_size) {
    const float* Q = (const float*)d_in[0];
    const float* K = (const float*)d_in[1];
    const float* V = (const float*)d_in[2];
    float* out = (float*)d_out;

    const int smem_bytes =
        (RT * KSTR + WWIN * KSTR + EN * VTSTR + RT * SWSTR + ZMAX) * (int)sizeof(float);
    cudaFuncSetAttribute(anomaly_attn_kernel,
                         cudaFuncAttributeMaxDynamicSharedMemorySize, smem_bytes);

    dim3 grid(GRID);    // persistent: 128 CTAs x 4 tiles
    dim3 block(512);
    anomaly_attn_kernel<<<grid, block, smem_bytes>>>(Q, K, V, out);
}